// round 4
// baseline (speedup 1.0000x reference)
#include <cuda_runtime.h>
#include <cuda_bf16.h>
#include <cstdint>

// Problem constants (fixed by the dataset)
#define NN 50000
#define EE 800000
#define IN_C 256
#define HID_C 128
#define OUT_C 64

// ---------------------------------------------------------------------------
// Scratch (device globals -- no cudaMalloc allowed).
// Everything touched by float4 (128-bit) accesses is explicitly 16B-aligned
// (default float[] symbol alignment is 4B; LDG.E.128 on 4B alignment traps).
// ---------------------------------------------------------------------------
__device__ int   g_deg[NN];
__device__ float g_dinv[NN];
__device__ int   g_rowptr[NN + 1];
__device__ int   g_cursor[NN];
__device__ int   g_blocksums[64];
__device__ int   g_csr[EE];
__device__ __align__(16) float g_h1[(size_t)NN * HID_C];   // (x@W1)*dinv[row]
__device__ __align__(16) float g_t1[(size_t)NN * HID_C];   // relu(agg1 + b1)
__device__ __align__(16) float g_h2[(size_t)NN * OUT_C];   // (t1@W2)*dinv[row]

// ---------------------------------------------------------------------------
// Degree / norm.  edge_index is INT32: jax.random.randint(dtype=int64) is
// silently downgraded to int32 when x64 is disabled (reference never enables
// it), so the harness buffer is 2*EE int32 values. Reading it as int64 was
// the R3 illegal-memory-access.
// ---------------------------------------------------------------------------
__global__ void k_clear_deg() {
    int i = blockIdx.x * blockDim.x + threadIdx.x;
    if (i < NN) g_deg[i] = 0;
}

__global__ void k_count_deg(const int* __restrict__ dst) {
    int e = blockIdx.x * blockDim.x + threadIdx.x;
    if (e < EE) {
        unsigned d = (unsigned)dst[e];
        if (d < NN) atomicAdd(&g_deg[d], 1);
    }
}

__global__ void k_dinv() {
    int i = blockIdx.x * blockDim.x + threadIdx.x;
    if (i < NN) g_dinv[i] = rsqrtf((float)(g_deg[i] + 1));  // +1 self-loop
}

// ---------------------------------------------------------------------------
// Exclusive scan of g_deg -> g_rowptr (3-kernel scan, 49 blocks of 1024)
// ---------------------------------------------------------------------------
__global__ void k_scan_block() {
    __shared__ int sm[1024];
    int i = blockIdx.x * 1024 + threadIdx.x;
    int v = (i < NN) ? g_deg[i] : 0;
    sm[threadIdx.x] = v;
    __syncthreads();
#pragma unroll
    for (int off = 1; off < 1024; off <<= 1) {
        int t = (threadIdx.x >= off) ? sm[threadIdx.x - off] : 0;
        __syncthreads();
        sm[threadIdx.x] += t;
        __syncthreads();
    }
    int incl = sm[threadIdx.x];
    if (i < NN) g_rowptr[i] = incl - v;            // exclusive within block
    if (threadIdx.x == 1023) g_blocksums[blockIdx.x] = incl;
}

__global__ void k_scan_sums(int nb) {
    if (threadIdx.x == 0 && blockIdx.x == 0) {
        int acc = 0;
        for (int b = 0; b < nb; b++) {
            int v = g_blocksums[b];
            g_blocksums[b] = acc;
            acc += v;
        }
    }
}

__global__ void k_scan_add() {
    int i = blockIdx.x * blockDim.x + threadIdx.x;
    if (i < NN) {
        int r = g_rowptr[i] + g_blocksums[i >> 10];
        g_rowptr[i] = r;
        g_cursor[i] = r;
    }
    if (i == 0) g_rowptr[NN] = EE;
}

__global__ void k_fill_csr(const int* __restrict__ src,
                           const int* __restrict__ dst) {
    int e = blockIdx.x * blockDim.x + threadIdx.x;
    if (e < EE) {
        unsigned d = (unsigned)dst[e];
        unsigned s = (unsigned)src[e];
        if (d < NN && s < NN) {
            int pos = atomicAdd(&g_cursor[d], 1);
            if ((unsigned)pos < EE) g_csr[pos] = (int)s;
        }
    }
}

// ---------------------------------------------------------------------------
// GEMM core: C[row, :] = (A[row, :] @ W) * g_dinv[row]
//   A: M x K row-major, W: K x BN row-major, single column tile (N == BN).
// ---------------------------------------------------------------------------
template <int BM, int BN, int BK, int TM, int TN>
__device__ __forceinline__ void gemm_rowscale_core(
        const float* __restrict__ A, const float* __restrict__ W,
        float* __restrict__ C, int M, int K) {
    constexpr int THREADS = (BM / TM) * (BN / TN);
    __shared__ __align__(16) float As[BK][BM + 4];
    __shared__ __align__(16) float Ws[BK][BN];

    const int tid = threadIdx.x;
    const int tx  = tid % (BN / TN);
    const int ty  = tid / (BN / TN);
    const int rowBase = blockIdx.x * BM;

    float acc[TM][TN];
#pragma unroll
    for (int i = 0; i < TM; i++)
#pragma unroll
        for (int j = 0; j < TN; j++) acc[i][j] = 0.f;

    for (int k0 = 0; k0 < K; k0 += BK) {
        constexpr int A4 = BM * BK / 4;
#pragma unroll
        for (int i = tid; i < A4; i += THREADS) {
            int r  = i / (BK / 4);
            int kq = i % (BK / 4);
            int grow = rowBase + r;
            float4 v = make_float4(0.f, 0.f, 0.f, 0.f);
            if (grow < M)
                v = *reinterpret_cast<const float4*>(A + (size_t)grow * K + k0 + kq * 4);
            As[kq * 4 + 0][r] = v.x;
            As[kq * 4 + 1][r] = v.y;
            As[kq * 4 + 2][r] = v.z;
            As[kq * 4 + 3][r] = v.w;
        }
        constexpr int W4 = BK * BN / 4;
#pragma unroll
        for (int i = tid; i < W4; i += THREADS) {
            int kk = i / (BN / 4);
            int nq = i % (BN / 4);
            float4 v = *reinterpret_cast<const float4*>(W + (size_t)(k0 + kk) * BN + nq * 4);
            *reinterpret_cast<float4*>(&Ws[kk][nq * 4]) = v;
        }
        __syncthreads();

#pragma unroll
        for (int k = 0; k < BK; k++) {
            float af[TM], bf[TN];
#pragma unroll
            for (int i = 0; i < TM; i++) af[i] = As[k][ty * TM + i];
#pragma unroll
            for (int j = 0; j < TN; j++) bf[j] = Ws[k][tx * TN + j];
#pragma unroll
            for (int i = 0; i < TM; i++)
#pragma unroll
                for (int j = 0; j < TN; j++) acc[i][j] += af[i] * bf[j];
        }
        __syncthreads();
    }

#pragma unroll
    for (int i = 0; i < TM; i++) {
        int grow = rowBase + ty * TM + i;
        if (grow < M) {
            float s = g_dinv[grow];
#pragma unroll
            for (int j = 0; j < TN; j++)
                C[(size_t)grow * BN + tx * TN + j] = acc[i][j] * s;
        }
    }
}

__global__ void __launch_bounds__(128)
k_gemm1(const float* __restrict__ x, const float* __restrict__ W1) {
    gemm_rowscale_core<64, HID_C, 32, 8, 8>(x, W1, g_h1, NN, IN_C);
}

__global__ void __launch_bounds__(128)
k_gemm2(const float* __restrict__ W2) {
    gemm_rowscale_core<64, OUT_C, 32, 8, 4>(g_t1, W2, g_h2, NN, HID_C);
}

// ---------------------------------------------------------------------------
// Aggregation: out[i] = act( dinv[i] * (hs[i] + sum_{s in N(i)} hs[s]) + bias )
//   One group of C/4 threads per node; float4 per thread.
// ---------------------------------------------------------------------------
template <int C, bool RELU>
__device__ __forceinline__ void aggregate_core(
        const float* __restrict__ hs, const float* __restrict__ bias,
        float* __restrict__ out) {
    constexpr int G   = C / 4;     // threads per node
    constexpr int NPB = 128 / G;   // nodes per block
    const int local = threadIdx.x / G;
    const int lane  = threadIdx.x % G;
    const int node  = blockIdx.x * NPB + local;
    if (node >= NN) return;

    const float4* base = reinterpret_cast<const float4*>(hs);
    float4 acc = base[(size_t)node * G + lane];    // self-loop term
    const int beg = g_rowptr[node];
    const int end = g_rowptr[node + 1];
    for (int e = beg; e < end; e++) {
        int s = g_csr[e];
        float4 v = base[(size_t)s * G + lane];
        acc.x += v.x; acc.y += v.y; acc.z += v.z; acc.w += v.w;
    }
    const float d = g_dinv[node];
    float4 b = reinterpret_cast<const float4*>(bias)[lane];
    acc.x = acc.x * d + b.x;
    acc.y = acc.y * d + b.y;
    acc.z = acc.z * d + b.z;
    acc.w = acc.w * d + b.w;
    if (RELU) {
        acc.x = fmaxf(acc.x, 0.f);
        acc.y = fmaxf(acc.y, 0.f);
        acc.z = fmaxf(acc.z, 0.f);
        acc.w = fmaxf(acc.w, 0.f);
    }
    reinterpret_cast<float4*>(out)[(size_t)node * G + lane] = acc;
}

__global__ void __launch_bounds__(128)
k_agg1(const float* __restrict__ b1) {
    aggregate_core<HID_C, true>(g_h1, b1, g_t1);
}

__global__ void __launch_bounds__(128)
k_agg2(const float* __restrict__ b2, float* __restrict__ out) {
    aggregate_core<OUT_C, false>(g_h2, b2, out);
}

// ---------------------------------------------------------------------------
// Launch
// ---------------------------------------------------------------------------
extern "C" void kernel_launch(void* const* d_in, const int* in_sizes, int n_in,
                              void* d_out, int out_size) {
    const float* x   = (const float*)d_in[0];
    const int*   ei  = (const int*)d_in[1];     // int32! (JAX x64 disabled)
    const float* W1  = (const float*)d_in[2];
    const float* b1  = (const float*)d_in[3];
    const float* W2  = (const float*)d_in[4];
    const float* b2  = (const float*)d_in[5];
    float*       out = (float*)d_out;

    const int* src = ei;         // edge_index[0]
    const int* dst = ei + EE;    // edge_index[1]

    const int TB = 256;
    const int nBlkN = (NN + TB - 1) / TB;
    const int nBlkE = (EE + TB - 1) / TB;
    const int nScan = (NN + 1023) / 1024;  // 49

    // --- normalization + CSR build ---
    k_clear_deg<<<nBlkN, TB>>>();
    k_count_deg<<<nBlkE, TB>>>(dst);
    k_dinv<<<nBlkN, TB>>>();
    k_scan_block<<<nScan, 1024>>>();
    k_scan_sums<<<1, 32>>>(nScan);
    k_scan_add<<<nBlkN, TB>>>();
    k_fill_csr<<<nBlkE, TB>>>(src, dst);

    // --- layer 1: h1 = (x @ W1) * dinv[row] ---
    {
        constexpr int BM = 64;
        int grid = (NN + BM - 1) / BM;
        k_gemm1<<<grid, 128>>>(x, W1);
    }
    // t1 = relu(dinv * (A_hat gather of h1) + b1)
    {
        constexpr int NPB = 128 / (HID_C / 4);  // 4 nodes / block
        int grid = (NN + NPB - 1) / NPB;
        k_agg1<<<grid, 128>>>(b1);
    }
    // --- layer 2: h2 = (t1 @ W2) * dinv[row] ---
    {
        constexpr int BM = 64;
        int grid = (NN + BM - 1) / BM;
        k_gemm2<<<grid, 128>>>(W2);
    }
    // out = dinv * (A_hat gather of h2) + b2
    {
        constexpr int NPB = 128 / (OUT_C / 4);  // 8 nodes / block
        int grid = (NN + NPB - 1) / NPB;
        k_agg2<<<grid, 128>>>(b2, out);
    }
}